// round 7
// baseline (speedup 1.0000x reference)
#include <cuda_runtime.h>
#include <cstdint>
#include <cmath>

// Problem shapes (from reference setup_inputs):
//   x:       [B=64, C=256, W=64, H=64]  f32
//   weight:  [F=512, C=256, K=3, K=3]   f32
//   epsilon: [S, F, C, K, K]            f32   (S derived from sizes; S=1 here)
//   out:     [S, B, F, W, H]            f32
//
// Key identity: kernel dims k,l never index x, so
//   Weff[s,f,c] = sum_{k,l} tanh(w[f,c,k,l] + 0.5*log(eps/(1-eps)))
//   out[s,b,f,n] = sum_c Weff[s,f,c] * x[b,c,n],  n = w*H + h  (N = 4096)

#define F_DIM 512
#define C_DIM 256
#define B_DIM 64
#define N_DIM 4096
#define KK_DIM 9
#define MAX_S 4

__device__ float g_weff[MAX_S * F_DIM * C_DIM];

// ---------------------------------------------------------------------------
// Kernel 1: effective weights (tiny: S*F*C threads, 9 tanh/log each)
// ---------------------------------------------------------------------------
__global__ void weff_kernel(const float* __restrict__ w,
                            const float* __restrict__ eps, int S) {
    int i = blockIdx.x * blockDim.x + threadIdx.x;
    int total = S * F_DIM * C_DIM;
    if (i >= total) return;
    int fc = i % (F_DIM * C_DIM);
    const float* wp = w + (size_t)fc * KK_DIM;
    const float* ep = eps + (size_t)i * KK_DIM;
    float acc = 0.0f;
#pragma unroll
    for (int j = 0; j < KK_DIM; j++) {
        float e = ep[j];
        float d = 0.5f * logf(e / (1.0f - e));   // logistic noise
        acc += tanhf(wp[j] + d);                 // TAU = 1
    }
    g_weff[i] = acc;
}

// ---------------------------------------------------------------------------
// Packed fp32x2 helpers (sm_103a packed-FP32 pipe; 2x FFMA throughput)
// ---------------------------------------------------------------------------
__device__ __forceinline__ unsigned long long pack2(float v) {
    unsigned long long r;
    unsigned int u = __float_as_uint(v);
    asm("mov.b64 %0, {%1, %1};" : "=l"(r) : "r"(u));
    return r;
}
__device__ __forceinline__ void ffma2(unsigned long long& d,
                                      unsigned long long a,
                                      unsigned long long b) {
    asm("fma.rn.f32x2 %0, %1, %2, %3;" : "=l"(d) : "l"(a), "l"(b), "l"(d));
}

// ---------------------------------------------------------------------------
// Kernel 2: batched GEMM  out[bz][f][n] = sum_c Weff[s][f][c] * x[b][c][n]
//   Block tile: 128(M=f) x 128(N=n) x 16(K=c), 256 threads, 8x8 microtile.
//   Microtile split 4+4 at offsets {base, base+64} -> conflict-free LDS.128.
//   Accumulators packed as f32x2 pairs along N. Double-buffered SMEM,
//   one __syncthreads per K-step, global loads prefetched into registers.
// ---------------------------------------------------------------------------
__global__ void __launch_bounds__(256, 2)
gemm_kernel(const float* __restrict__ x, float* __restrict__ out) {
    __shared__ float As[2][16][132];   // [k][m], stride 132 softens STS conflicts
    __shared__ float Bs[2][16][128];   // [k][n]

    const int tid = threadIdx.x;
    const int bn0 = blockIdx.x * 128;
    const int bm0 = blockIdx.y * 128;
    const int bz  = blockIdx.z;                // s*B + b
    const int s   = bz / B_DIM;
    const int b   = bz % B_DIM;

    const float* A  = g_weff + (size_t)s * F_DIM * C_DIM;  // [F][C] row-major
    const float* Bx = x + (size_t)b * C_DIM * N_DIM;       // [C][N] row-major
    float* O = out + (size_t)bz * (size_t)F_DIM * N_DIM;

    // A-tile loader: 128 rows x 16 cols = 512 float4, 2/thread
    const int a_row = tid >> 2;             // 0..63 (+64 for i=1)
    const int a_col = (tid & 3) << 2;       // 0,4,8,12
    // B-tile loader: 16 rows x 128 cols = 512 float4, 2/thread (fully coalesced)
    const int b_row = tid >> 5;             // 0..7 (+8 for i=1)
    const int b_col = (tid & 31) << 2;

    // Microtile coords
    const int tn = (tid & 15) << 2;         // n base: {tn, tn+64}
    const int tm = (tid >> 4) << 2;         // m base: {tm, tm+64}

    const float* Ab = A  + (size_t)(bm0 + a_row) * C_DIM + a_col;
    const float* Bb = Bx + (size_t)b_row * N_DIM + bn0 + b_col;

    unsigned long long acc[8][4];
#pragma unroll
    for (int i = 0; i < 8; i++)
#pragma unroll
        for (int j = 0; j < 4; j++) acc[i][j] = 0ull;

    // Prologue: load K-step 0
    float4 ar0 = *(const float4*)(Ab);
    float4 ar1 = *(const float4*)(Ab + 64 * C_DIM);
    float4 br0 = *(const float4*)(Bb);
    float4 br1 = *(const float4*)(Bb + 8 * (size_t)N_DIM);

    As[0][a_col + 0][a_row] = ar0.x;  As[0][a_col + 1][a_row] = ar0.y;
    As[0][a_col + 2][a_row] = ar0.z;  As[0][a_col + 3][a_row] = ar0.w;
    As[0][a_col + 0][a_row + 64] = ar1.x;  As[0][a_col + 1][a_row + 64] = ar1.y;
    As[0][a_col + 2][a_row + 64] = ar1.z;  As[0][a_col + 3][a_row + 64] = ar1.w;
    *(float4*)&Bs[0][b_row][b_col]     = br0;
    *(float4*)&Bs[0][b_row + 8][b_col] = br1;
    __syncthreads();

    int buf = 0;
#pragma unroll 1
    for (int t = 0; t < 16; ++t) {
        // Prefetch next K-step to registers (latency hidden behind compute)
        if (t < 15) {
            int k = (t + 1) * 16;
            ar0 = *(const float4*)(Ab + k);
            ar1 = *(const float4*)(Ab + 64 * C_DIM + k);
            br0 = *(const float4*)(Bb + (size_t)k * N_DIM);
            br1 = *(const float4*)(Bb + (size_t)(k + 8) * N_DIM);
        }

        const float (*Asc)[132] = As[buf];
        const float (*Bsc)[128] = Bs[buf];
#pragma unroll
        for (int kk = 0; kk < 16; ++kk) {
            float4 a0 = *(const float4*)&Asc[kk][tm];        // warp-broadcast
            float4 a1 = *(const float4*)&Asc[kk][tm + 64];
            ulonglong2 b0v = *(const ulonglong2*)&Bsc[kk][tn];      // conflict-free
            ulonglong2 b1v = *(const ulonglong2*)&Bsc[kk][tn + 64];
            unsigned long long bp0 = b0v.x, bp1 = b0v.y;
            unsigned long long bp2 = b1v.x, bp3 = b1v.y;
            float am[8] = {a0.x, a0.y, a0.z, a0.w, a1.x, a1.y, a1.z, a1.w};
#pragma unroll
            for (int i = 0; i < 8; i++) {
                unsigned long long ap = pack2(am[i]);
                ffma2(acc[i][0], ap, bp0);
                ffma2(acc[i][1], ap, bp1);
                ffma2(acc[i][2], ap, bp2);
                ffma2(acc[i][3], ap, bp3);
            }
        }

        if (t < 15) {
            int nb = buf ^ 1;
            As[nb][a_col + 0][a_row] = ar0.x;  As[nb][a_col + 1][a_row] = ar0.y;
            As[nb][a_col + 2][a_row] = ar0.z;  As[nb][a_col + 3][a_row] = ar0.w;
            As[nb][a_col + 0][a_row + 64] = ar1.x;  As[nb][a_col + 1][a_row + 64] = ar1.y;
            As[nb][a_col + 2][a_row + 64] = ar1.z;  As[nb][a_col + 3][a_row + 64] = ar1.w;
            *(float4*)&Bs[nb][b_row][b_col]     = br0;
            *(float4*)&Bs[nb][b_row + 8][b_col] = br1;
        }
        __syncthreads();
        buf ^= 1;
    }

    // Epilogue: unpack f32x2 pairs, vectorized STG.128
#pragma unroll
    for (int i = 0; i < 8; i++) {
        int m = bm0 + ((i < 4) ? (tm + i) : (tm + 60 + i));  // tm+i or tm+64+(i-4)
        float* op = O + (size_t)m * N_DIM + bn0;
        float2 p0 = *reinterpret_cast<float2*>(&acc[i][0]);
        float2 p1 = *reinterpret_cast<float2*>(&acc[i][1]);
        float2 p2 = *reinterpret_cast<float2*>(&acc[i][2]);
        float2 p3 = *reinterpret_cast<float2*>(&acc[i][3]);
        *(float4*)(op + tn)      = make_float4(p0.x, p0.y, p1.x, p1.y);
        *(float4*)(op + tn + 64) = make_float4(p2.x, p2.y, p3.x, p3.y);
    }
}

// ---------------------------------------------------------------------------
// Launch: inputs in metadata order: x, weight, epsilon
// ---------------------------------------------------------------------------
extern "C" void kernel_launch(void* const* d_in, const int* in_sizes, int n_in,
                              void* d_out, int out_size) {
    const float* x   = (const float*)d_in[0];
    const float* w   = (const float*)d_in[1];
    const float* eps = (const float*)d_in[2];
    float* out = (float*)d_out;

    int S = in_sizes[2] / in_sizes[1];
    if (S < 1) S = 1;
    if (S > MAX_S) S = MAX_S;

    int total = S * F_DIM * C_DIM;
    weff_kernel<<<(total + 255) / 256, 256>>>(w, eps, S);

    dim3 grid(N_DIM / 128, F_DIM / 128, S * B_DIM);
    gemm_kernel<<<grid, 256>>>(x, out);
}

// round 9
// speedup vs baseline: 1.1159x; 1.1159x over previous
#include <cuda_runtime.h>
#include <cuda_bf16.h>
#include <cstdint>
#include <cmath>

// Problem:
//   x:       [B=64, C=256, W*H=4096]  f32
//   weight:  [F=512, C=256, 3, 3]     f32
//   epsilon: [S, F, C, 3, 3]          f32
//   out:     [S, B, F, 4096]          f32
//
// Identity: kernel dims never index x ->
//   Weff[s,f,c] = sum_{k,l} tanh(w[f,c,k,l] + 0.5*log(eps/(1-eps)))
//   out[s,b,f,n] = sum_c Weff[s,f,c] * x[b,c,n]   (batched 512x4096x256 GEMM)
//
// tcgen05 is compile-blocked (harness targets compute_103, not 103a), so this
// round uses mma.sync.m16n8k16 bf16 (HMMA) with hi/lo split-precision:
//   a = ah + al (bf16 each); out = ah*bh + ah*bl + al*bh  (fp32 accum)
// Dropped al*bl term ~2^-18 relative -> rel_err ~1e-5 << 1e-3.

#define F_DIM 512
#define C_DIM 256
#define B_DIM 64
#define N_DIM 4096
#define KK_DIM 9
#define MAX_S 4

#define TM 128
#define TN 64
#define TK 64
#define NCHUNK (C_DIM / TK)     // 4

// SMEM tile rows padded to 144B (72 bf16): ldmatrix rows land on distinct
// bank groups (stride 36 words -> +4 banks/row -> conflict-free 16B reads).
#define ROWB 144
#define A_TILE_B (128 * ROWB)   // 18432
#define B_TILE_B (64 * ROWB)    // 9216
#define OFF_AH 0
#define OFF_AL A_TILE_B
#define OFF_BH (2 * A_TILE_B)
#define OFF_BL (2 * A_TILE_B + B_TILE_B)
#define STAGE_B (2 * A_TILE_B + 2 * B_TILE_B)   // 55296
#define SMEM_SZ (2 * STAGE_B)                   // 110592

__device__ __nv_bfloat16 g_wh[MAX_S * F_DIM * C_DIM];
__device__ __nv_bfloat16 g_wl[MAX_S * F_DIM * C_DIM];

// ---------------------------------------------------------------------------
// Kernel 1: effective weights -> bf16 hi/lo split
// ---------------------------------------------------------------------------
__global__ void weff_kernel(const float* __restrict__ w,
                            const float* __restrict__ eps, int S) {
    int i = blockIdx.x * blockDim.x + threadIdx.x;
    int total = S * F_DIM * C_DIM;
    if (i >= total) return;
    int fc = i % (F_DIM * C_DIM);
    const float* wp = w + (size_t)fc * KK_DIM;
    const float* ep = eps + (size_t)i * KK_DIM;
    float acc = 0.0f;
#pragma unroll
    for (int j = 0; j < KK_DIM; j++) {
        float e = ep[j];
        float d = 0.5f * logf(e / (1.0f - e));
        acc += tanhf(wp[j] + d);
    }
    __nv_bfloat16 h = __float2bfloat16_rn(acc);
    g_wh[i] = h;
    g_wl[i] = __float2bfloat16_rn(acc - __bfloat162float(h));
}

// ---------------------------------------------------------------------------
// Helpers
// ---------------------------------------------------------------------------
__device__ __forceinline__ uint32_t smem_u32(const void* p) {
    uint32_t a;
    asm("{ .reg .u64 t; cvta.to.shared.u64 t, %1; cvt.u32.u64 %0, t; }"
        : "=r"(a) : "l"(p));
    return a;
}
__device__ __forceinline__ void stsv4(uint32_t a, uint32_t x, uint32_t y,
                                      uint32_t z, uint32_t w) {
    asm volatile("st.shared.v4.b32 [%0], {%1,%2,%3,%4};"
                 :: "r"(a), "r"(x), "r"(y), "r"(z), "r"(w));
}
#define LDM4(r, addr)                                                       \
    asm volatile("ldmatrix.sync.aligned.m8n8.x4.shared.b16 "                \
                 "{%0,%1,%2,%3}, [%4];"                                     \
                 : "=r"((r)[0]), "=r"((r)[1]), "=r"((r)[2]), "=r"((r)[3])   \
                 : "r"(addr))
#define MMA(c, a, b0, b1)                                                   \
    asm volatile("mma.sync.aligned.m16n8k16.row.col.f32.bf16.bf16.f32 "     \
                 "{%0,%1,%2,%3}, {%4,%5,%6,%7}, {%8,%9}, {%0,%1,%2,%3};"    \
                 : "+f"((c)[0]), "+f"((c)[1]), "+f"((c)[2]), "+f"((c)[3])   \
                 : "r"((a)[0]), "r"((a)[1]), "r"((a)[2]), "r"((a)[3]),      \
                   "r"(b0), "r"(b1))

__device__ __forceinline__ uint32_t pack_bf16(float f0, float f1) {
    __nv_bfloat16 h0 = __float2bfloat16_rn(f0);
    __nv_bfloat16 h1 = __float2bfloat16_rn(f1);
    return (uint32_t)__bfloat16_as_ushort(h0) |
           ((uint32_t)__bfloat16_as_ushort(h1) << 16);
}

// ---------------------------------------------------------------------------
// Kernel 2: HMMA split-bf16 GEMM. CTA 128(M=f) x 64(N=n), K chunks of 64.
// 8 warps as 4(m) x 2(n); each warp 32x32 -> 2x4 m16n8 mma tiles, 3 passes.
// Double-buffered SMEM + register prefetch; one __syncthreads per chunk.
// ---------------------------------------------------------------------------
__global__ void __launch_bounds__(256, 1)
gemm_mma(const float* __restrict__ x, float* __restrict__ out) {
    extern __shared__ char smem[];
    const uint32_t sb = smem_u32(smem);
    const int tid = threadIdx.x;
    const int wid = tid >> 5, lane = tid & 31;

    const int n0 = blockIdx.x * TN;
    const int m0 = blockIdx.y * TM;
    const int bz = blockIdx.z;                  // s*64 + b
    const int s = bz >> 6, b = bz & 63;

    const __nv_bfloat16* Agh = g_wh + (size_t)s * F_DIM * C_DIM;
    const __nv_bfloat16* Agl = g_wl + (size_t)s * F_DIM * C_DIM;
    const float* X = x + (size_t)b * C_DIM * N_DIM;

    // ---- loader assignments ----
    // A: tid<128 -> hi row tid; tid>=128 -> lo row tid-128. 128B/row contiguous.
    const int ar = tid & 127;
    const int asel = tid >> 7;                          // 0 hi, 1 lo
    const __nv_bfloat16* Asrc =
        (asel ? Agl : Agh) + (size_t)(m0 + ar) * C_DIM;
    const uint32_t a_dst = sb + (asel ? OFF_AL : OFF_AH) + (uint32_t)ar * ROWB;
    // B: thread owns column n=tid&63, c-group of 16. Gmem loads coalesced
    // (64 lanes x 4B = 256B per c-row); convert fp32 -> bf16 hi/lo; store
    // transposed into Bs[n][c] (32B contiguous per thread).
    const int bn = tid & 63;
    const int bc = (tid >> 6) * 16;
    const uint32_t b_dst = sb + OFF_BH + (uint32_t)bn * ROWB + (uint32_t)bc * 2;

    // ---- per-warp mma tile bases ----
    const int mb = (wid & 3) * 32;                      // m quarter
    const int nb = (wid >> 2) * 32;                     // n half
    const int lj = lane >> 3, lr = lane & 7;
    // ldmatrix per-lane byte offsets within a tile (A: x4 = a0..a3 order;
    // B: x4 = two n8 tiles' {b0,b1})
    uint32_t aoff[2], boff[2];
#pragma unroll
    for (int mt = 0; mt < 2; mt++)
        aoff[mt] = (uint32_t)((mb + mt * 16 + lr + (lj & 1) * 8) * ROWB +
                              (lj >> 1) * 16);
#pragma unroll
    for (int np = 0; np < 2; np++)
        boff[np] = (uint32_t)((nb + np * 16 + lr + (lj >> 1) * 8) * ROWB +
                              (lj & 1) * 16);

    float acc[2][4][4];
#pragma unroll
    for (int mt = 0; mt < 2; mt++)
#pragma unroll
        for (int nt = 0; nt < 4; nt++)
#pragma unroll
            for (int q = 0; q < 4; q++) acc[mt][nt][q] = 0.0f;

    // ---- prologue: chunk 0 straight into buffer 0 ----
    {
        const uint4* s4 = (const uint4*)Asrc;
#pragma unroll
        for (int q = 0; q < 8; q++) {
            uint4 v = s4[q];
            stsv4(a_dst + q * 16, v.x, v.y, v.z, v.w);
        }
        float v[16];
#pragma unroll
        for (int jc = 0; jc < 16; jc++)
            v[jc] = __ldg(X + (size_t)(bc + jc) * N_DIM + n0 + bn);
        uint32_t hp[8], lp[8];
#pragma unroll
        for (int i = 0; i < 8; i++) {
            float f0 = v[2 * i], f1 = v[2 * i + 1];
            hp[i] = pack_bf16(f0, f1);
            float r0 = f0 - __bfloat162float(__float2bfloat16_rn(f0));
            float r1 = f1 - __bfloat162float(__float2bfloat16_rn(f1));
            lp[i] = pack_bf16(r0, r1);
        }
        stsv4(b_dst, hp[0], hp[1], hp[2], hp[3]);
        stsv4(b_dst + 16, hp[4], hp[5], hp[6], hp[7]);
        stsv4(b_dst + B_TILE_B, lp[0], lp[1], lp[2], lp[3]);
        stsv4(b_dst + B_TILE_B + 16, lp[4], lp[5], lp[6], lp[7]);
    }
    __syncthreads();

    uint4 pa[8];
    float pb[16];

#pragma unroll 1
    for (int t = 0; t < NCHUNK; t++) {
        // prefetch next chunk to registers
        if (t < NCHUNK - 1) {
            const int c0n = (t + 1) * TK;
            const uint4* s4 = (const uint4*)(Asrc + c0n);
#pragma unroll
            for (int q = 0; q < 8; q++) pa[q] = s4[q];
#pragma unroll
            for (int jc = 0; jc < 16; jc++)
                pb[jc] = __ldg(X + (size_t)(c0n + bc + jc) * N_DIM + n0 + bn);
        }

        // compute chunk t from buffer (t&1)
        const uint32_t bufb = sb + (uint32_t)(t & 1) * STAGE_B;
#pragma unroll
        for (int k = 0; k < 4; k++) {
            uint32_t ah[2][4], al[2][4], bh[2][4], bl[2][4];
#pragma unroll
            for (int mt = 0; mt < 2; mt++) {
                LDM4(ah[mt], bufb + OFF_AH + aoff[mt] + k * 32);
                LDM4(al[mt], bufb + OFF_AL + aoff[mt] + k * 32);
            }
#pragma unroll
            for (int np = 0; np < 2; np++) {
                LDM4(bh[np], bufb + OFF_BH + boff[np] + k * 32);
                LDM4(bl[np], bufb + OFF_BL + boff[np] + k * 32);
            }
#pragma unroll
            for (int mt = 0; mt < 2; mt++)
#pragma unroll
                for (int nt = 0; nt < 4; nt++) {
                    const int np = nt >> 1, i = (nt & 1) * 2;
                    MMA(acc[mt][nt], ah[mt], bh[np][i], bh[np][i + 1]);
                    MMA(acc[mt][nt], ah[mt], bl[np][i], bl[np][i + 1]);
                    MMA(acc[mt][nt], al[mt], bh[np][i], bh[np][i + 1]);
                }
        }

        // store prefetched chunk into the other buffer
        if (t < NCHUNK - 1) {
            const uint32_t ob = (uint32_t)((t + 1) & 1) * STAGE_B;
#pragma unroll
            for (int q = 0; q < 8; q++)
                stsv4(a_dst + ob + q * 16, pa[q].x, pa[q].y, pa[q].z, pa[q].w);
            uint32_t hp[8], lp[8];
#pragma unroll
            for (int i = 0; i < 8; i++) {
                float f0 = pb[2 * i], f1 = pb[2 * i + 1];
                hp[i] = pack_bf16(f0, f1);
                float r0 = f0 - __bfloat162float(__float2bfloat16_rn(f0));
                float r1 = f1 - __bfloat162float(__float2bfloat16_rn(f1));
                lp[i] = pack_bf16(r0, r1);
            }
            stsv4(b_dst + ob, hp[0], hp[1], hp[2], hp[3]);
            stsv4(b_dst + ob + 16, hp[4], hp[5], hp[6], hp[7]);
            stsv4(b_dst + ob + B_TILE_B, lp[0], lp[1], lp[2], lp[3]);
            stsv4(b_dst + ob + B_TILE_B + 16, lp[4], lp[5], lp[6], lp[7]);
        }
        __syncthreads();
    }

    // ---- epilogue: direct f32 stores (aligned 8B per thread, 32B sectors) ----
#pragma unroll
    for (int mt = 0; mt < 2; mt++)
#pragma unroll
        for (int nt = 0; nt < 4; nt++) {
            const int row = m0 + mb + mt * 16 + (lane >> 2);
            const int col = n0 + nb + nt * 8 + (lane & 3) * 2;
            float* op = out + ((size_t)bz * F_DIM + row) * N_DIM + col;
            *(float2*)op = make_float2(acc[mt][nt][0], acc[mt][nt][1]);
            *(float2*)(op + 8 * N_DIM) =
                make_float2(acc[mt][nt][2], acc[mt][nt][3]);
        }
}

// ---------------------------------------------------------------------------
// Launch: inputs in metadata order: x, weight, epsilon
// ---------------------------------------------------------------------------
extern "C" void kernel_launch(void* const* d_in, const int* in_sizes, int n_in,
                              void* d_out, int out_size) {
    const float* x   = (const float*)d_in[0];
    const float* w   = (const float*)d_in[1];
    const float* eps = (const float*)d_in[2];
    float* out = (float*)d_out;

    int S = in_sizes[2] / in_sizes[1];
    if (S < 1) S = 1;
    if (S > MAX_S) S = MAX_S;

    int total = S * F_DIM * C_DIM;
    weff_kernel<<<(total + 255) / 256, 256>>>(w, eps, S);

    cudaFuncSetAttribute(gemm_mma, cudaFuncAttributeMaxDynamicSharedMemorySize,
                         SMEM_SZ);
    dim3 grid(N_DIM / TN, F_DIM / TM, S * B_DIM);
    gemm_mma<<<grid, 256, SMEM_SZ>>>(x, out);
}